// round 5
// baseline (speedup 1.0000x reference)
#include <cuda_runtime.h>
#include <math.h>

#define H 1024
#define L 4096
#define V 29
#define NB 148
#define NT 512
#define WPB 16
#define WTOT (NB * WPB)        // 2368 warps

// ---------------- scratch (device globals) ----------------------------------
__device__ float g_scp0[L];            // score partials, half 0 (emb)
__device__ float g_scp1[L];            // score partials, half 1 (h0)
__device__ float g_hh[4 * H];          // W_hh @ h0
__device__ float g_attn_applied[H];
__device__ float g_xp[2 * H];          // comb partials [row][half]
__device__ float g_gates[4 * H];
__device__ unsigned g_cnt = 0;
__device__ volatile unsigned g_flag = 0;

// ---------------- helpers ----------------------------------------------------
__device__ __forceinline__ float warp_sum(float v) {
#pragma unroll
    for (int o = 16; o; o >>= 1) v += __shfl_xor_sync(0xffffffffu, v, o);
    return v;
}
__device__ __forceinline__ float warp_max(float v) {
#pragma unroll
    for (int o = 16; o; o >>= 1) v = fmaxf(v, __shfl_xor_sync(0xffffffffu, v, o));
    return v;
}
__device__ __forceinline__ float sigmoidf_(float x) { return 1.0f / (1.0f + expf(-x)); }
__device__ __forceinline__ float dot4(float4 a, float4 b) {
    return a.x * b.x + a.y * b.y + a.z * b.z + a.w * b.w;
}

__device__ __forceinline__ void grid_barrier(unsigned sense) {
    __syncthreads();
    if (threadIdx.x == 0) {
        __threadfence();
        unsigned old = atomicAdd(&g_cnt, 1u);
        if (old == NB - 1) {
            g_cnt = 0;
            __threadfence();
            g_flag = sense;
        } else {
            while (g_flag != sense) { __nanosleep(32); }
        }
        __threadfence();
    }
    __syncthreads();
}

// 1024-elt dot against an 8xfloat4 register vector (no shared memory)
#define DOT_REG(wp, vreg, accv)                                    \
    do {                                                           \
        float _a0 = 0.f, _a1 = 0.f;                                \
        _Pragma("unroll")                                          \
        for (int _k = 0; _k < 8; _k += 2) {                        \
            _a0 += dot4((wp)[lane + 32 * _k],       (vreg)[_k]);   \
            _a1 += dot4((wp)[lane + 32 * (_k + 1)], (vreg)[_k+1]); \
        }                                                          \
        (accv) = _a0 + _a1;                                        \
    } while (0)

// ---------------- the whole decoder step in one kernel -----------------------
__global__ void __launch_bounds__(NT, 1)
k_decoder(const int* __restrict__ tok,
          const float* __restrict__ h0,
          const float* __restrict__ c0,
          const float* __restrict__ enc,
          const float* __restrict__ emb,
          const float* __restrict__ attn_W,
          const float* __restrict__ attn_b,
          const float* __restrict__ comb_W,
          const float* __restrict__ comb_b,
          const float* __restrict__ W_ih,
          const float* __restrict__ W_hh,
          const float* __restrict__ b_ih,
          const float* __restrict__ b_hh,
          const float* __restrict__ out_W,
          const float* __restrict__ out_b,
          float* __restrict__ out) {
    __shared__ float s[2 * H];         // multipurpose: col partials / x / h
    __shared__ float red[16];
    __shared__ float bcast;
    __shared__ float wts[28];
    __shared__ float z[32];

    const int t = threadIdx.x;
    const int warp = t >> 5, lane = t & 31;
    const int wg = blockIdx.x * WPB + warp;   // 0..2367
    float* attn_out = out + V + 2 * H;        // [lp | h | c | attn_w]

    // persistent register vectors: vA = emb row, vB = h0 (later attn, x)
    float4 vA[8], vB[8];
    {
        const float4* ef = (const float4*)(emb + (size_t)tok[0] * H);
        const float4* hf = (const float4*)h0;
#pragma unroll
        for (int k = 0; k < 8; k++) { vA[k] = ef[lane + 32 * k]; vB[k] = hf[lane + 32 * k]; }
    }
    if (blockIdx.x == 0) { g_attn_applied[t] = 0.0f; g_attn_applied[t + 512] = 0.0f; }

    // ===== Phase A: scores halves (8192) + W_hh rows (4096) = 12288 chunks ==
    {
        unsigned c0i = (unsigned)(((unsigned long long)wg * 12288ull) / WTOT);
        unsigned c1i = (unsigned)(((unsigned long long)(wg + 1) * 12288ull) / WTOT);
        for (unsigned c = c0i; c < c1i; c++) {
            float acc;
            if (c < 4096u) {                       // score half0 (v = emb)
                const float4* wp = (const float4*)(attn_W + (size_t)c * (2 * H));
                DOT_REG(wp, vA, acc);
                acc = warp_sum(acc);
                if (lane == 0) g_scp0[c] = acc;
            } else if (c < 8192u) {                // score half1 (v = h0)
                unsigned r = c - 4096u;
                const float4* wp = (const float4*)(attn_W + (size_t)r * (2 * H) + H);
                DOT_REG(wp, vB, acc);
                acc = warp_sum(acc);
                if (lane == 0) g_scp1[r] = acc;
            } else {                               // hh row (v = h0)
                unsigned r = c - 8192u;
                const float4* wp = (const float4*)(W_hh + (size_t)r * H);
                DOT_REG(wp, vB, acc);
                acc = warp_sum(acc);
                if (lane == 0) g_hh[r] = acc;
            }
        }
    }
    grid_barrier(1);

    // ===== Phase B: softmax (redundant per-block reduce) + weighted enc sum =
    {
        float sc[8];
        float m = -1e30f;
#pragma unroll
        for (int k = 0; k < 8; k++) {
            int i = t + k * 512;
            sc[k] = g_scp0[i] + g_scp1[i] + attn_b[i];
            m = fmaxf(m, sc[k]);
        }
        m = warp_max(m);
        if (lane == 0) red[warp] = m;
        __syncthreads();
        if (warp == 0) {
            float x = (lane < 16) ? red[lane] : -1e30f;
            x = warp_max(x);
            if (lane == 0) bcast = x;
        }
        __syncthreads();
        const float M = bcast;

        float sum = 0.0f;
#pragma unroll
        for (int k = 0; k < 8; k++) sum += expf(sc[k] - M);
        sum = warp_sum(sum);
        __syncthreads();
        if (lane == 0) red[warp] = sum;
        __syncthreads();
        if (warp == 0) {
            float x = (lane < 16) ? red[lane] : 0.0f;
            x = warp_sum(x);
            if (lane == 0) bcast = x;
        }
        __syncthreads();
        const float invS = 1.0f / bcast;

        const int lb = blockIdx.x * 28;
        const int nr = (lb < L) ? min(28, L - lb) : 0;
        if (t < nr) {
            float w = expf(g_scp0[lb + t] + g_scp1[lb + t] + attn_b[lb + t] - M) * invS;
            wts[t] = w;
            attn_out[lb + t] = w;
        }
        __syncthreads();

        if (nr > 0) {
            float4* sb = (float4*)s;               // 256 float4 partials
            int grp = t >> 8, col = t & 255;       // 2 row-groups x 256 cols
            const float4* ef = (const float4*)enc;
            float4 acc = make_float4(0.f, 0.f, 0.f, 0.f);
            int rs = grp * 14, re = min(rs + 14, nr);
            for (int r = rs; r < re; r++) {
                float4 v = ef[(size_t)(lb + r) * 256 + col];
                float w = wts[r];
                acc.x += w * v.x; acc.y += w * v.y; acc.z += w * v.z; acc.w += w * v.w;
            }
            if (grp == 1) sb[col] = acc;
            __syncthreads();
            if (grp == 0) {
                float4 o = sb[col];
                acc.x += o.x; acc.y += o.y; acc.z += o.z; acc.w += o.w;
                float* dst = g_attn_applied + 4 * col;
                atomicAdd(dst + 0, acc.x);
                atomicAdd(dst + 1, acc.y);
                atomicAdd(dst + 2, acc.z);
                atomicAdd(dst + 3, acc.w);
            }
        }
    }
    grid_barrier(0);

    // ===== Phase C: comb partials = comb_W @ [emb; attn] (2048 half chunks) =
    {
        const float4* af = (const float4*)g_attn_applied;
#pragma unroll
        for (int k = 0; k < 8; k++) vB[k] = af[lane + 32 * k];   // vB = attn

        if (wg < 2 * H) {
            int row = wg >> 1, half = wg & 1;
            const float4* wp = (const float4*)(comb_W + (size_t)row * (2 * H) + half * H);
            float acc;
            if (half == 0) { DOT_REG(wp, vA, acc); }
            else           { DOT_REG(wp, vB, acc); }
            acc = warp_sum(acc);
            if (lane == 0) g_xp[wg] = acc;
        }
    }
    grid_barrier(1);

    // ===== Phase D: gates = W_ih @ x (+hh +biases), x rebuilt into regs =====
    {
        // x into shared once per block (8 KB from L2), then regs per warp
        const float4* xpf = (const float4*)g_xp;
        float4 p = xpf[t];                 // rows 2t, 2t+1
        s[2 * t]     = fmaxf(p.x + p.y + comb_b[2 * t],     0.0f);
        s[2 * t + 1] = fmaxf(p.z + p.w + comb_b[2 * t + 1], 0.0f);
        __syncthreads();
        const float4* sf = (const float4*)s;
#pragma unroll
        for (int k = 0; k < 8; k++) vB[k] = sf[lane + 32 * k];   // vB = x

        unsigned r0 = (unsigned)(((unsigned long long)wg * 4096ull) / WTOT);
        unsigned r1 = (unsigned)(((unsigned long long)(wg + 1) * 4096ull) / WTOT);
        for (unsigned r = r0; r < r1; r++) {
            const float4* wp = (const float4*)(W_ih + (size_t)r * H);
            float acc;
            DOT_REG(wp, vB, acc);
            acc = warp_sum(acc);
            if (lane == 0) g_gates[r] = acc + g_hh[r] + b_ih[r] + b_hh[r];
        }
    }
    grid_barrier(0);

    // ===== Phase E: LSTM pointwise + out proj + log_softmax (block 0) =======
    if (blockIdx.x == 0) {
        for (int i = t; i < H; i += NT) {
            float ig = g_gates[i];
            float fg = g_gates[H + i];
            float gg = g_gates[2 * H + i];
            float og = g_gates[3 * H + i];
            float c = sigmoidf_(fg) * c0[i] + sigmoidf_(ig) * tanhf(gg);
            float h = sigmoidf_(og) * tanhf(c);
            out[V + i] = h;
            out[V + H + i] = c;
            s[i] = h;
        }
        __syncthreads();

        const float4* hv = (const float4*)s;
        for (int row = warp; row < V; row += WPB) {
            const float4* wr = (const float4*)(out_W + (size_t)row * H);
            float acc = 0.0f;
#pragma unroll
            for (int k = lane; k < H / 4; k += 32) acc += dot4(wr[k], hv[k]);
            acc = warp_sum(acc);
            if (lane == 0) z[row] = acc + out_b[row];
        }
        __syncthreads();

        if (t == 0) {
            float m = -1e30f;
            for (int r = 0; r < V; r++) m = fmaxf(m, z[r]);
            float ssum = 0.0f;
            for (int r = 0; r < V; r++) ssum += expf(z[r] - m);
            float ls = m + logf(ssum);
            for (int r = 0; r < V; r++) out[r] = z[r] - ls;
        }
    }
}

// ---------------- launch ------------------------------------------------------
extern "C" void kernel_launch(void* const* d_in, const int* in_sizes, int n_in,
                              void* d_out, int out_size) {
    const int*   tok    = (const int*)  d_in[0];
    const float* h0     = (const float*)d_in[1];
    const float* c0     = (const float*)d_in[2];
    const float* enc    = (const float*)d_in[3];
    const float* emb    = (const float*)d_in[4];
    const float* attn_W = (const float*)d_in[5];
    const float* attn_b = (const float*)d_in[6];
    const float* comb_W = (const float*)d_in[7];
    const float* comb_b = (const float*)d_in[8];
    const float* W_ih   = (const float*)d_in[9];
    const float* W_hh   = (const float*)d_in[10];
    const float* b_ih   = (const float*)d_in[11];
    const float* b_hh   = (const float*)d_in[12];
    const float* out_W  = (const float*)d_in[13];
    const float* out_b  = (const float*)d_in[14];
    float* out = (float*)d_out;

    k_decoder<<<NB, NT>>>(tok, h0, c0, enc, emb, attn_W, attn_b,
                          comb_W, comb_b, W_ih, W_hh, b_ih, b_hh,
                          out_W, out_b, out);
}